// round 6
// baseline (speedup 1.0000x reference)
#include <cuda_runtime.h>

// NCM R6: no weight staging — weights read via __ldg (L1-cached, identical
// across CTAs). SMEM = activations only (64KB/CTA -> 2 CTAs/SM, L1 carveout
// ~100KB holds a full node's 41.5KB weights). R5 warp tile: 16 samples =
// 8 f32x2 pairs/warp, lane owns 2 output cols. 256 CTAs x 256 threads.

#define TPB    256
#define NBLK   256
#define NNODES 32

typedef unsigned long long u64;

__device__ __forceinline__ u64 fma2(u64 a, u64 b, u64 c) {
    u64 d; asm("fma.rn.f32x2 %0,%1,%2,%3;" : "=l"(d) : "l"(a), "l"(b), "l"(c));
    return d;
}
__device__ __forceinline__ u64 dup2(float x) {
    u64 d; asm("mov.b64 %0,{%1,%1};" : "=l"(d) : "f"(x)); return d;
}
__device__ __forceinline__ void unpk(u64 a, float& lo, float& hi) {
    asm("mov.b64 {%0,%1},%2;" : "=f"(lo), "=f"(hi) : "l"(a));
}
__device__ __forceinline__ u64 pk(float lo, float hi) {
    u64 d; asm("mov.b64 %0,{%1,%2};" : "=l"(d) : "f"(lo), "f"(hi)); return d;
}
__device__ __forceinline__ u64 relu2(u64 a) {
    float lo, hi; unpk(a, lo, hi);
    return pk(fmaxf(lo, 0.0f), fmaxf(hi, 0.0f));
}

// per-warp SMEM: ring u64[8][64] | h u64[8][64] (u aliased into h cols 0..15)
#define WARP_U64 1024
#define SMEM_BYTES (8 * WARP_U64 * 8)   // 65536

__global__ void __launch_bounds__(TPB, 2) ncm_kernel(
    const float* __restrict__ u,
    const float* __restrict__ w_r1, const float* __restrict__ b_r1,
    const float* __restrict__ w_r2, const float* __restrict__ b_r2,
    const float* __restrict__ w_r3, const float* __restrict__ b_r3,
    const float* __restrict__ w_i1, const float* __restrict__ b_i1,
    const float* __restrict__ w_i2, const float* __restrict__ b_i2,
    const float* __restrict__ w_i3, const float* __restrict__ b_i3,
    float* __restrict__ out)
{
    extern __shared__ u64 sm[];

    const int tid = threadIdx.x;
    const int wp = tid >> 5, l = tid & 31;
    const int q8 = l & 7;    // L3: output dims (2q8, 2q8+1)
    const int g  = l >> 3;   // L3: pairs 2g, 2g+1

    u64* s_ring = sm + wp * WARP_U64;   // [8][64]: [pair][slot*16+dim]
    u64* s_h    = s_ring + 512;         // [8][64]; u lives in cols 0..15

    const long sbase = (long)blockIdx.x * 128 + wp * 16;

    u64 acc0[8], acc1[8];

    for (int node = 0; node < NNODES; ++node) {
        const bool root = (node < 4);
        const float *g1, *g2, *g3, *gb1, *gb2, *gb3;
        if (root) {
            g1 = w_r1 + node * (16 * 64);
            g2 = w_r2 + node * (64 * 64);
            g3 = w_r3 + node * (64 * 16);
            gb1 = b_r1 + node * 64; gb2 = b_r2 + node * 64; gb3 = b_r3 + node * 16;
        } else {
            const int j = node - 4;
            g1 = w_i1 + j * (80 * 64);
            g2 = w_i2 + j * (64 * 64);
            g3 = w_i3 + j * (64 * 16);
            gb1 = b_i1 + j * 64; gb2 = b_i2 + j * 64; gb3 = b_i3 + j * 16;
        }

        // light convergence barrier: keeps all warps of the CTA on the same
        // node so the node's 41.5KB of weights stay L1-resident.
        __syncthreads();

        // ---- stage u (2 lanes per sample) into h-buffer cols 0..15 ----
        {
            const int sw = l >> 1;       // sample-in-warp 0..15
            const int hf = l & 1;        // dim half: 8*hf..8*hf+7
            const float* up = u + (sbase + sw) * (NNODES * 16) + node * 16 + 8 * hf;
            float* inf = (float*)(s_h + (sw >> 1) * 64);
            const int c = sw & 1;        // half of the f32x2 pair
            #pragma unroll
            for (int dd = 0; dd < 8; dd += 4) {
                float4 v4 = *(const float4*)(up + dd);
                inf[(8 * hf + dd + 0) * 2 + c] = v4.x;
                inf[(8 * hf + dd + 1) * 2 + c] = v4.y;
                inf[(8 * hf + dd + 2) * 2 + c] = v4.z;
                inf[(8 * hf + dd + 3) * 2 + c] = v4.w;
            }
        }
        __syncwarp();

        // inner block: weights via __ldg (L1-hit; contiguous 256B per k),
        // acts = broadcast u64 sample-pairs from per-warp SMEM, 2 k per iter.
        auto mm = [&](const float* W, const u64* act, int kcount) {
            #pragma unroll 2
            for (int kk = 0; kk < kcount; kk += 2) {
                float2 wa = __ldg((const float2*)(W + kk * 64) + l);
                float2 wb = __ldg((const float2*)(W + (kk + 1) * 64) + l);
                const u64 A0 = dup2(wa.x), A1 = dup2(wa.y);
                const u64 B0 = dup2(wb.x), B1 = dup2(wb.y);
                #pragma unroll
                for (int p = 0; p < 8; ++p) {
                    ulonglong2 xx = *(const ulonglong2*)(act + p * 64 + kk);
                    acc0[p] = fma2(xx.x, A0, acc0[p]);
                    acc0[p] = fma2(xx.y, B0, acc0[p]);
                    acc1[p] = fma2(xx.x, A1, acc1[p]);
                    acc1[p] = fma2(xx.y, B1, acc1[p]);
                }
            }
        };

        auto relu_store = [&]() {
            #pragma unroll
            for (int p = 0; p < 8; ++p) {
                ulonglong2 r;
                r.x = relu2(acc0[p]); r.y = relu2(acc1[p]);
                *(ulonglong2*)(s_h + p * 64 + 2 * l) = r;
            }
        };

        // ---- layer 1 ----
        {
            float2 bb = __ldg((const float2*)gb1 + l);
            const u64 d0 = dup2(bb.x), d1 = dup2(bb.y);
            #pragma unroll
            for (int p = 0; p < 8; ++p) { acc0[p] = d0; acc1[p] = d1; }
        }
        if (!root) {
            #pragma unroll 1
            for (int q = 0; q < 4; ++q)
                mm(g1 + (q * 16) * 64, s_ring + ((node + q) & 3) * 16, 16);
            mm(g1 + 64 * 64, s_h, 16);    // u part (h cols 0..15)
        } else {
            mm(g1, s_h, 16);
        }
        __syncwarp();      // all u reads done before h overwrites cols 0..15
        relu_store();
        __syncwarp();

        // ---- layer 2 (in-place h) ----
        {
            float2 bb = __ldg((const float2*)gb2 + l);
            const u64 d0 = dup2(bb.x), d1 = dup2(bb.y);
            #pragma unroll
            for (int p = 0; p < 8; ++p) { acc0[p] = d0; acc1[p] = d1; }
        }
        mm(g2, s_h, 64);
        __syncwarp();      // all lanes done reading old h
        relu_store();
        __syncwarp();

        // ---- layer 3: lane (q8,g) -> dims (2q8,2q8+1), pairs 2g,2g+1 ----
        u64 c0[2], c1[2];
        {
            float2 b3v = __ldg((const float2*)gb3 + q8);
            const u64 d0 = dup2(b3v.x), d1 = dup2(b3v.y);
            c0[0] = d0; c0[1] = d0; c1[0] = d1; c1[1] = d1;
        }
        #pragma unroll 2
        for (int kk = 0; kk < 64; kk += 2) {
            float2 wa = __ldg((const float2*)(g3 + kk * 16) + q8);
            float2 wb = __ldg((const float2*)(g3 + (kk + 1) * 16) + q8);
            const u64 A0 = dup2(wa.x), A1 = dup2(wa.y);
            const u64 B0 = dup2(wb.x), B1 = dup2(wb.y);
            #pragma unroll
            for (int pl = 0; pl < 2; ++pl) {
                ulonglong2 xx =
                    *(const ulonglong2*)(s_h + (2 * g + pl) * 64 + kk);
                c0[pl] = fma2(xx.x, A0, c0[pl]);
                c0[pl] = fma2(xx.y, B0, c0[pl]);
                c1[pl] = fma2(xx.x, A1, c1[pl]);
                c1[pl] = fma2(xx.y, B1, c1[pl]);
            }
        }

        // ---- emit: logits (float2, coalesced) + thresholded ring bits ----
        const int slot = (node & 3) * 16;
        #pragma unroll
        for (int pl = 0; pl < 2; ++pl) {
            const int p = 2 * g + pl;
            const long s0 = sbase + 2 * p;
            float v00, v01, v10, v11;
            unpk(c0[pl], v00, v01);   // dim 2q8,  samples (2p, 2p+1)
            unpk(c1[pl], v10, v11);   // dim 2q8+1
            float2* o0 = (float2*)(out + s0 * (NNODES * 16) + node * 16 + 2 * q8);
            float2* o1 = (float2*)((float*)o0 + NNODES * 16);
            *o0 = make_float2(v00, v10);
            *o1 = make_float2(v01, v11);
            s_ring[p * 64 + slot + 2 * q8] =
                pk(v00 > 0.5f ? 1.0f : 0.0f, v01 > 0.5f ? 1.0f : 0.0f);
            s_ring[p * 64 + slot + 2 * q8 + 1] =
                pk(v10 > 0.5f ? 1.0f : 0.0f, v11 > 0.5f ? 1.0f : 0.0f);
        }
        __syncwarp();   // ring writes visible before next node's layer-1 reads
    }
}

extern "C" void kernel_launch(void* const* d_in, const int* in_sizes, int n_in,
                              void* d_out, int out_size) {
    (void)in_sizes; (void)n_in; (void)out_size;
    cudaFuncSetAttribute(ncm_kernel, cudaFuncAttributeMaxDynamicSharedMemorySize,
                         SMEM_BYTES);
    ncm_kernel<<<NBLK, TPB, SMEM_BYTES>>>(
        (const float*)d_in[0],
        (const float*)d_in[1], (const float*)d_in[2],
        (const float*)d_in[3], (const float*)d_in[4],
        (const float*)d_in[5], (const float*)d_in[6],
        (const float*)d_in[7], (const float*)d_in[8],
        (const float*)d_in[9], (const float*)d_in[10],
        (const float*)d_in[11], (const float*)d_in[12],
        (float*)d_out);
}

// round 8
// speedup vs baseline: 1.6175x; 1.6175x over previous
#include <cuda_runtime.h>

// NCM R8: R7 with staging bugfix (w3 copy 256 x 16B, was 128 — half of w3
// was garbage). R2 compute tile (warp = 32 samples = 16 f32x2 pairs, lane =
// 2 cols) + cp.async double-buffered weight staging overlapped with compute
// + u prefetched one node ahead + one barrier per node. 128 CTAs x 256 thr.

#define TPB    256
#define NBLK   128
#define NNODES 32

typedef unsigned long long u64;
typedef unsigned int u32;

__device__ __forceinline__ u64 fma2(u64 a, u64 b, u64 c) {
    u64 d; asm("fma.rn.f32x2 %0,%1,%2,%3;" : "=l"(d) : "l"(a), "l"(b), "l"(c));
    return d;
}
__device__ __forceinline__ u64 dup2(float x) {
    u64 d; asm("mov.b64 %0,{%1,%1};" : "=l"(d) : "f"(x)); return d;
}
__device__ __forceinline__ void unpk(u64 a, float& lo, float& hi) {
    asm("mov.b64 {%0,%1},%2;" : "=f"(lo), "=f"(hi) : "l"(a));
}
__device__ __forceinline__ u64 pk(float lo, float hi) {
    u64 d; asm("mov.b64 %0,{%1,%2};" : "=l"(d) : "f"(lo), "f"(hi)); return d;
}
__device__ __forceinline__ u64 relu2(u64 a) {
    float lo, hi; unpk(a, lo, hi);
    return pk(fmaxf(lo, 0.0f), fmaxf(hi, 0.0f));
}
__device__ __forceinline__ void cpa16(u32 dst, const float* src) {
    asm volatile("cp.async.cg.shared.global [%0], [%1], 16;"
                 :: "r"(dst), "l"(src));
}

// per-buffer u64 offsets: W1 0 | W2 2560 | W3 4608 | B1 5120 | B2 5152 | B3 5184
#define BUFSZ 5192
// byte offsets inside buffer
#define BW2 20480
#define BW3 36864
#define BB1 40960
#define BB2 41216
#define BB3 41472
#define ACT (2 * BUFSZ)                 // 10384 u64
// per-warp acts: ring u64[16][66] | h u64[16][66] (u aliased into h cols 0..15)
#define ASTR 66
#define WARP_U64 (2 * 16 * ASTR)        // 2112
#define SMEM_BYTES ((ACT + 8 * WARP_U64) * 8)   // 218240

__global__ void __launch_bounds__(TPB, 1) ncm_kernel(
    const float* __restrict__ u,
    const float* __restrict__ w_r1, const float* __restrict__ b_r1,
    const float* __restrict__ w_r2, const float* __restrict__ b_r2,
    const float* __restrict__ w_r3, const float* __restrict__ b_r3,
    const float* __restrict__ w_i1, const float* __restrict__ b_i1,
    const float* __restrict__ w_i2, const float* __restrict__ b_i2,
    const float* __restrict__ w_i3, const float* __restrict__ b_i3,
    float* __restrict__ out)
{
    extern __shared__ u64 sm[];

    const int tid = threadIdx.x;
    const int wp = tid >> 5, l = tid & 31;
    const int q8 = l & 7;    // L3: output dims (2q8, 2q8+1)
    const int g  = l >> 3;   // L3: pairs 4g..4g+3

    u64* s_ring = sm + ACT + wp * WARP_U64;   // [16][66]: [pair][slot*16+dim]
    u64* s_h    = s_ring + 16 * ASTR;         // [16][66]; u in cols 0..15

    const long sbase = (long)blockIdx.x * TPB + wp * 32;

    // stage node nx's weights into buf via cp.async (+ commit)
    auto stage = [&](int nx, u64* buf) {
        const bool rt = nx < 4;
        const float *G1, *G2, *G3, *GB1, *GB2, *GB3;
        if (rt) {
            G1 = w_r1 + nx * 1024; G2 = w_r2 + nx * 4096; G3 = w_r3 + nx * 1024;
            GB1 = b_r1 + nx * 64; GB2 = b_r2 + nx * 64; GB3 = b_r3 + nx * 16;
        } else {
            const int j = nx - 4;
            G1 = w_i1 + j * 5120; G2 = w_i2 + j * 4096; G3 = w_i3 + j * 1024;
            GB1 = b_i1 + j * 64; GB2 = b_i2 + j * 64; GB3 = b_i3 + j * 16;
        }
        const u32 base = (u32)__cvta_generic_to_shared(buf);
        const int c1 = rt ? 256 : 1280;
        for (int i = tid; i < c1; i += TPB)   cpa16(base + i * 16, G1 + i * 4);
        for (int i = tid; i < 1024; i += TPB) cpa16(base + BW2 + i * 16, G2 + i * 4);
        for (int i = tid; i < 256; i += TPB)  cpa16(base + BW3 + i * 16, G3 + i * 4);
        if (tid < 16)                   cpa16(base + BB1 + tid * 16, GB1 + tid * 4);
        else if (tid >= 32 && tid < 48) cpa16(base + BB2 + (tid - 32) * 16, GB2 + (tid - 32) * 4);
        else if (tid >= 64 && tid < 68) cpa16(base + BB3 + (tid - 64) * 16, GB3 + (tid - 64) * 4);
        asm volatile("cp.async.commit_group;" ::: "memory");
    };

    // u prefetch registers: lane l = sample sbase+l, 16 dims
    float4 pu0, pu1, pu2, pu3;
    auto ldu = [&](int nx) {
        const float4* up =
            (const float4*)(u + (sbase + l) * (NNODES * 16) + nx * 16);
        pu0 = up[0]; pu1 = up[1]; pu2 = up[2]; pu3 = up[3];
    };

    // prologue: stage node 0 weights, prefetch node 0 u
    stage(0, sm);
    ldu(0);

    u64 acc0[16], acc1[16];

    for (int node = 0; node < NNODES; ++node) {
        u64* wb = sm + (node & 1) * BUFSZ;
        const float* w1 = (const float*)(wb);
        const float* w2 = (const float*)(wb + 2560);
        const float* w3 = (const float*)(wb + 4608);
        const float* b1 = (const float*)(wb + 5120);
        const float* b2 = (const float*)(wb + 5152);
        const float* b3 = (const float*)(wb + 5184);

        asm volatile("cp.async.wait_group 0;" ::: "memory");
        __syncthreads();   // weights ready; prev node's reads of other buf done

        if (node + 1 < NNODES)
            stage(node + 1, sm + ((node + 1) & 1) * BUFSZ);

        // ---- store prefetched u into h cols 0..15 (no LDG stall) ----
        {
            float* inf = (float*)(s_h + (l >> 1) * ASTR);
            const int c = l & 1;
            float uu[16] = {pu0.x, pu0.y, pu0.z, pu0.w,
                            pu1.x, pu1.y, pu1.z, pu1.w,
                            pu2.x, pu2.y, pu2.z, pu2.w,
                            pu3.x, pu3.y, pu3.z, pu3.w};
            #pragma unroll
            for (int dd = 0; dd < 16; ++dd) inf[dd * 2 + c] = uu[dd];
        }
        __syncwarp();

        // R2 inner block: weights (lane's cols 2l,2l+1) from SMEM buffer,
        // acts = broadcast u64 sample-pairs, 2 k per iteration.
        auto mm = [&](const float* W, const u64* act, int kcount) {
            #pragma unroll 1
            for (int kk = 0; kk < kcount; kk += 2) {
                float2 wa = *(const float2*)(W + kk * 64 + 2 * l);
                float2 wb2 = *(const float2*)(W + (kk + 1) * 64 + 2 * l);
                const u64 A0 = dup2(wa.x), A1 = dup2(wa.y);
                const u64 B0 = dup2(wb2.x), B1 = dup2(wb2.y);
                #pragma unroll
                for (int p = 0; p < 16; ++p) {
                    ulonglong2 xx = *(const ulonglong2*)(act + p * ASTR + kk);
                    acc0[p] = fma2(xx.x, A0, acc0[p]);
                    acc0[p] = fma2(xx.y, B0, acc0[p]);
                    acc1[p] = fma2(xx.x, A1, acc1[p]);
                    acc1[p] = fma2(xx.y, B1, acc1[p]);
                }
            }
        };

        auto relu_store = [&]() {
            #pragma unroll
            for (int p = 0; p < 16; ++p) {
                ulonglong2 r;
                r.x = relu2(acc0[p]); r.y = relu2(acc1[p]);
                *(ulonglong2*)(s_h + p * ASTR + 2 * l) = r;
            }
        };

        // ---- layer 1 ----
        {
            float2 bb = *(const float2*)(b1 + 2 * l);
            const u64 d0 = dup2(bb.x), d1 = dup2(bb.y);
            #pragma unroll
            for (int p = 0; p < 16; ++p) { acc0[p] = d0; acc1[p] = d1; }
        }
        if (node >= 4) {
            #pragma unroll 1
            for (int q = 0; q < 4; ++q)
                mm(w1 + (q * 16) * 64, s_ring + ((node + q) & 3) * 16, 16);
            mm(w1 + 64 * 64, s_h, 16);       // u part (h cols 0..15)
        } else {
            mm(w1, s_h, 16);
        }
        __syncwarp();     // u reads done before relu_store overwrites cols 0..15
        relu_store();
        __syncwarp();

        // prefetch next node's u (covered by layers 2+3)
        if (node + 1 < NNODES) ldu(node + 1);

        // ---- layer 2 (in-place h) ----
        {
            float2 bb = *(const float2*)(b2 + 2 * l);
            const u64 d0 = dup2(bb.x), d1 = dup2(bb.y);
            #pragma unroll
            for (int p = 0; p < 16; ++p) { acc0[p] = d0; acc1[p] = d1; }
        }
        mm(w2, s_h, 64);
        __syncwarp();     // all lanes done reading old h
        relu_store();
        __syncwarp();

        // ---- layer 3: lane (q8,g) -> dims (2q8,2q8+1), pairs 4g..4g+3 ----
        u64 c0[4], c1[4];
        {
            const u64 d0 = dup2(b3[2 * q8]), d1 = dup2(b3[2 * q8 + 1]);
            #pragma unroll
            for (int pl = 0; pl < 4; ++pl) { c0[pl] = d0; c1[pl] = d1; }
        }
        #pragma unroll 1
        for (int kk = 0; kk < 64; kk += 2) {
            float2 wa = *(const float2*)(w3 + kk * 16 + 2 * q8);
            float2 wb3 = *(const float2*)(w3 + (kk + 1) * 16 + 2 * q8);
            const u64 A0 = dup2(wa.x), A1 = dup2(wa.y);
            const u64 B0 = dup2(wb3.x), B1 = dup2(wb3.y);
            #pragma unroll
            for (int pl = 0; pl < 4; ++pl) {
                ulonglong2 xx =
                    *(const ulonglong2*)(s_h + (4 * g + pl) * ASTR + kk);
                c0[pl] = fma2(xx.x, A0, c0[pl]);
                c0[pl] = fma2(xx.y, B0, c0[pl]);
                c1[pl] = fma2(xx.x, A1, c1[pl]);
                c1[pl] = fma2(xx.y, B1, c1[pl]);
            }
        }

        // ---- emit: logits to gmem + thresholded ring bits ----
        const int slot = (node & 3) * 16;
        #pragma unroll
        for (int pl = 0; pl < 4; ++pl) {
            const int p = 4 * g + pl;
            const long s0 = sbase + 2 * p;
            float v00, v01, v10, v11;
            unpk(c0[pl], v00, v01);   // dim 2q8,  samples (2p, 2p+1)
            unpk(c1[pl], v10, v11);   // dim 2q8+1
            float2* o0 = (float2*)(out + s0 * (NNODES * 16) + node * 16 + 2 * q8);
            float2* o1 = (float2*)((float*)o0 + NNODES * 16);
            *o0 = make_float2(v00, v10);
            *o1 = make_float2(v01, v11);
            s_ring[p * ASTR + slot + 2 * q8] =
                pk(v00 > 0.5f ? 1.0f : 0.0f, v01 > 0.5f ? 1.0f : 0.0f);
            s_ring[p * ASTR + slot + 2 * q8 + 1] =
                pk(v10 > 0.5f ? 1.0f : 0.0f, v11 > 0.5f ? 1.0f : 0.0f);
        }
        __syncwarp();   // ring visible to whole warp before next node's layer 1
    }
}

extern "C" void kernel_launch(void* const* d_in, const int* in_sizes, int n_in,
                              void* d_out, int out_size) {
    (void)in_sizes; (void)n_in; (void)out_size;
    cudaFuncSetAttribute(ncm_kernel, cudaFuncAttributeMaxDynamicSharedMemorySize,
                         SMEM_BYTES);
    ncm_kernel<<<NBLK, TPB, SMEM_BYTES>>>(
        (const float*)d_in[0],
        (const float*)d_in[1], (const float*)d_in[2],
        (const float*)d_in[3], (const float*)d_in[4],
        (const float*)d_in[5], (const float*)d_in[6],
        (const float*)d_in[7], (const float*)d_in[8],
        (const float*)d_in[9], (const float*)d_in[10],
        (const float*)d_in[11], (const float*)d_in[12],
        (float*)d_out);
}

// round 9
// speedup vs baseline: 1.7068x; 1.0552x over previous
#include <cuda_runtime.h>

// NCM R9: R8 + full-chip spread. Grid 148 (one CTA per SM), warp tile 28
// samples = 14 f32x2 pairs; tail warps clamp sbase and duplicate-compute a
// few samples (identical values racing to identical addresses — benign).
// cp.async double-buffered weights, u prefetch, 1 barrier/node (R8 skeleton).

#define TPB    256
#define NBLK   148
#define NNODES 32
#define NP     14          // sample-pairs per warp
#define SPW    28          // samples per warp
#define SBMAX  (32768 - SPW)

typedef unsigned long long u64;
typedef unsigned int u32;

__device__ __forceinline__ u64 fma2(u64 a, u64 b, u64 c) {
    u64 d; asm("fma.rn.f32x2 %0,%1,%2,%3;" : "=l"(d) : "l"(a), "l"(b), "l"(c));
    return d;
}
__device__ __forceinline__ u64 dup2(float x) {
    u64 d; asm("mov.b64 %0,{%1,%1};" : "=l"(d) : "f"(x)); return d;
}
__device__ __forceinline__ void unpk(u64 a, float& lo, float& hi) {
    asm("mov.b64 {%0,%1},%2;" : "=f"(lo), "=f"(hi) : "l"(a));
}
__device__ __forceinline__ u64 pk(float lo, float hi) {
    u64 d; asm("mov.b64 %0,{%1,%2};" : "=l"(d) : "f"(lo), "f"(hi)); return d;
}
__device__ __forceinline__ u64 relu2(u64 a) {
    float lo, hi; unpk(a, lo, hi);
    return pk(fmaxf(lo, 0.0f), fmaxf(hi, 0.0f));
}
__device__ __forceinline__ void cpa16(u32 dst, const float* src) {
    asm volatile("cp.async.cg.shared.global [%0], [%1], 16;"
                 :: "r"(dst), "l"(src));
}

// per-buffer u64 offsets: W1 0 | W2 2560 | W3 4608 | B1 5120 | B2 5152 | B3 5184
#define BUFSZ 5192
// byte offsets inside buffer
#define BW2 20480
#define BW3 36864
#define BB1 40960
#define BB2 41216
#define BB3 41472
#define ACT (2 * BUFSZ)                 // 10384 u64
// per-warp acts: ring u64[NP][66] | h u64[NP][66] (u aliased into h cols 0..15)
#define ASTR 66
#define WARP_U64 (2 * NP * ASTR)        // 1848
#define SMEM_BYTES ((ACT + 8 * WARP_U64) * 8)   // 201344

__global__ void __launch_bounds__(TPB, 1) ncm_kernel(
    const float* __restrict__ u,
    const float* __restrict__ w_r1, const float* __restrict__ b_r1,
    const float* __restrict__ w_r2, const float* __restrict__ b_r2,
    const float* __restrict__ w_r3, const float* __restrict__ b_r3,
    const float* __restrict__ w_i1, const float* __restrict__ b_i1,
    const float* __restrict__ w_i2, const float* __restrict__ b_i2,
    const float* __restrict__ w_i3, const float* __restrict__ b_i3,
    float* __restrict__ out)
{
    extern __shared__ u64 sm[];

    const int tid = threadIdx.x;
    const int wp = tid >> 5, l = tid & 31;
    const int q8 = l & 7;    // L3: output dims (2q8, 2q8+1)
    const int g  = l >> 3;   // L3: pairs 4g..4g+3 (clamped to 13)

    u64* s_ring = sm + ACT + wp * WARP_U64;   // [NP][66]: [pair][slot*16+dim]
    u64* s_h    = s_ring + NP * ASTR;         // [NP][66]; u in cols 0..15

    // global warp id -> sample base, clamped (tail warps duplicate work)
    long sbase = (long)(blockIdx.x * 8 + wp) * SPW;
    if (sbase > SBMAX) sbase = SBMAX;

    // stage node nx's weights into buf via cp.async (+ commit)
    auto stage = [&](int nx, u64* buf) {
        const bool rt = nx < 4;
        const float *G1, *G2, *G3, *GB1, *GB2, *GB3;
        if (rt) {
            G1 = w_r1 + nx * 1024; G2 = w_r2 + nx * 4096; G3 = w_r3 + nx * 1024;
            GB1 = b_r1 + nx * 64; GB2 = b_r2 + nx * 64; GB3 = b_r3 + nx * 16;
        } else {
            const int j = nx - 4;
            G1 = w_i1 + j * 5120; G2 = w_i2 + j * 4096; G3 = w_i3 + j * 1024;
            GB1 = b_i1 + j * 64; GB2 = b_i2 + j * 64; GB3 = b_i3 + j * 16;
        }
        const u32 base = (u32)__cvta_generic_to_shared(buf);
        const int c1 = rt ? 256 : 1280;
        for (int i = tid; i < c1; i += TPB)   cpa16(base + i * 16, G1 + i * 4);
        for (int i = tid; i < 1024; i += TPB) cpa16(base + BW2 + i * 16, G2 + i * 4);
        for (int i = tid; i < 256; i += TPB)  cpa16(base + BW3 + i * 16, G3 + i * 4);
        if (tid < 16)                   cpa16(base + BB1 + tid * 16, GB1 + tid * 4);
        else if (tid >= 32 && tid < 48) cpa16(base + BB2 + (tid - 32) * 16, GB2 + (tid - 32) * 4);
        else if (tid >= 64 && tid < 68) cpa16(base + BB3 + (tid - 64) * 16, GB3 + (tid - 64) * 4);
        asm volatile("cp.async.commit_group;" ::: "memory");
    };

    // u prefetch registers: lane l (< SPW) = sample sbase+l, 16 dims
    float4 pu0, pu1, pu2, pu3;
    auto ldu = [&](int nx) {
        if (l < SPW) {
            const float4* up =
                (const float4*)(u + (sbase + l) * (NNODES * 16) + nx * 16);
            pu0 = up[0]; pu1 = up[1]; pu2 = up[2]; pu3 = up[3];
        }
    };

    // prologue
    stage(0, sm);
    ldu(0);

    u64 acc0[NP], acc1[NP];

    for (int node = 0; node < NNODES; ++node) {
        u64* wb = sm + (node & 1) * BUFSZ;
        const float* w1 = (const float*)(wb);
        const float* w2 = (const float*)(wb + 2560);
        const float* w3 = (const float*)(wb + 4608);
        const float* b1 = (const float*)(wb + 5120);
        const float* b2 = (const float*)(wb + 5152);
        const float* b3 = (const float*)(wb + 5184);

        asm volatile("cp.async.wait_group 0;" ::: "memory");
        __syncthreads();   // weights ready; prev node's reads of other buf done

        if (node + 1 < NNODES)
            stage(node + 1, sm + ((node + 1) & 1) * BUFSZ);

        // ---- store prefetched u into h cols 0..15 ----
        if (l < SPW) {
            float* inf = (float*)(s_h + (l >> 1) * ASTR);
            const int c = l & 1;
            float uu[16] = {pu0.x, pu0.y, pu0.z, pu0.w,
                            pu1.x, pu1.y, pu1.z, pu1.w,
                            pu2.x, pu2.y, pu2.z, pu2.w,
                            pu3.x, pu3.y, pu3.z, pu3.w};
            #pragma unroll
            for (int dd = 0; dd < 16; ++dd) inf[dd * 2 + c] = uu[dd];
        }
        __syncwarp();

        // R2/R8 inner block: weights (lane's cols 2l,2l+1), broadcast acts.
        auto mm = [&](const float* W, const u64* act, int kcount) {
            #pragma unroll 1
            for (int kk = 0; kk < kcount; kk += 2) {
                float2 wa = *(const float2*)(W + kk * 64 + 2 * l);
                float2 wb2 = *(const float2*)(W + (kk + 1) * 64 + 2 * l);
                const u64 A0 = dup2(wa.x), A1 = dup2(wa.y);
                const u64 B0 = dup2(wb2.x), B1 = dup2(wb2.y);
                #pragma unroll
                for (int p = 0; p < NP; ++p) {
                    ulonglong2 xx = *(const ulonglong2*)(act + p * ASTR + kk);
                    acc0[p] = fma2(xx.x, A0, acc0[p]);
                    acc0[p] = fma2(xx.y, B0, acc0[p]);
                    acc1[p] = fma2(xx.x, A1, acc1[p]);
                    acc1[p] = fma2(xx.y, B1, acc1[p]);
                }
            }
        };

        auto relu_store = [&]() {
            #pragma unroll
            for (int p = 0; p < NP; ++p) {
                ulonglong2 r;
                r.x = relu2(acc0[p]); r.y = relu2(acc1[p]);
                *(ulonglong2*)(s_h + p * ASTR + 2 * l) = r;
            }
        };

        // ---- layer 1 ----
        {
            float2 bb = *(const float2*)(b1 + 2 * l);
            const u64 d0 = dup2(bb.x), d1 = dup2(bb.y);
            #pragma unroll
            for (int p = 0; p < NP; ++p) { acc0[p] = d0; acc1[p] = d1; }
        }
        if (node >= 4) {
            #pragma unroll 1
            for (int q = 0; q < 4; ++q)
                mm(w1 + (q * 16) * 64, s_ring + ((node + q) & 3) * 16, 16);
            mm(w1 + 64 * 64, s_h, 16);       // u part (h cols 0..15)
        } else {
            mm(w1, s_h, 16);
        }
        __syncwarp();     // u reads done before relu_store overwrites cols 0..15
        relu_store();
        __syncwarp();

        // prefetch next node's u (covered by layers 2+3)
        if (node + 1 < NNODES) ldu(node + 1);

        // ---- layer 2 (in-place h) ----
        {
            float2 bb = *(const float2*)(b2 + 2 * l);
            const u64 d0 = dup2(bb.x), d1 = dup2(bb.y);
            #pragma unroll
            for (int p = 0; p < NP; ++p) { acc0[p] = d0; acc1[p] = d1; }
        }
        mm(w2, s_h, 64);
        __syncwarp();     // all lanes done reading old h
        relu_store();
        __syncwarp();

        // ---- layer 3: lane (q8,g) -> dims (2q8,2q8+1), pairs 4g..4g+3
        //      (pp clamped to NP-1; duplicate compute/stores are identical) ----
        u64 c0[4], c1[4];
        {
            const u64 d0 = dup2(b3[2 * q8]), d1 = dup2(b3[2 * q8 + 1]);
            #pragma unroll
            for (int pl = 0; pl < 4; ++pl) { c0[pl] = d0; c1[pl] = d1; }
        }
        int ppi[4];
        #pragma unroll
        for (int pl = 0; pl < 4; ++pl) {
            int pp = 4 * g + pl;
            ppi[pl] = pp > (NP - 1) ? (NP - 1) : pp;
        }
        #pragma unroll 1
        for (int kk = 0; kk < 64; kk += 2) {
            float2 wa = *(const float2*)(w3 + kk * 16 + 2 * q8);
            float2 wb3 = *(const float2*)(w3 + (kk + 1) * 16 + 2 * q8);
            const u64 A0 = dup2(wa.x), A1 = dup2(wa.y);
            const u64 B0 = dup2(wb3.x), B1 = dup2(wb3.y);
            #pragma unroll
            for (int pl = 0; pl < 4; ++pl) {
                ulonglong2 xx =
                    *(const ulonglong2*)(s_h + ppi[pl] * ASTR + kk);
                c0[pl] = fma2(xx.x, A0, c0[pl]);
                c0[pl] = fma2(xx.y, B0, c0[pl]);
                c1[pl] = fma2(xx.x, A1, c1[pl]);
                c1[pl] = fma2(xx.y, B1, c1[pl]);
            }
        }

        // ---- emit: logits to gmem + thresholded ring bits ----
        const int slot = (node & 3) * 16;
        #pragma unroll
        for (int pl = 0; pl < 4; ++pl) {
            const int p = ppi[pl];
            const long s0 = sbase + 2 * p;
            float v00, v01, v10, v11;
            unpk(c0[pl], v00, v01);   // dim 2q8,  samples (2p, 2p+1)
            unpk(c1[pl], v10, v11);   // dim 2q8+1
            float2* o0 = (float2*)(out + s0 * (NNODES * 16) + node * 16 + 2 * q8);
            float2* o1 = (float2*)((float*)o0 + NNODES * 16);
            *o0 = make_float2(v00, v10);
            *o1 = make_float2(v01, v11);
            s_ring[p * ASTR + slot + 2 * q8] =
                pk(v00 > 0.5f ? 1.0f : 0.0f, v01 > 0.5f ? 1.0f : 0.0f);
            s_ring[p * ASTR + slot + 2 * q8 + 1] =
                pk(v10 > 0.5f ? 1.0f : 0.0f, v11 > 0.5f ? 1.0f : 0.0f);
        }
        __syncwarp();   // ring visible to whole warp before next node's layer 1
    }
}

extern "C" void kernel_launch(void* const* d_in, const int* in_sizes, int n_in,
                              void* d_out, int out_size) {
    (void)in_sizes; (void)n_in; (void)out_size;
    cudaFuncSetAttribute(ncm_kernel, cudaFuncAttributeMaxDynamicSharedMemorySize,
                         SMEM_BYTES);
    ncm_kernel<<<NBLK, TPB, SMEM_BYTES>>>(
        (const float*)d_in[0],
        (const float*)d_in[1], (const float*)d_in[2],
        (const float*)d_in[3], (const float*)d_in[4],
        (const float*)d_in[5], (const float*)d_in[6],
        (const float*)d_in[7], (const float*)d_in[8],
        (const float*)d_in[9], (const float*)d_in[10],
        (const float*)d_in[11], (const float*)d_in[12],
        (float*)d_out);
}